// round 17
// baseline (speedup 1.0000x reference)
#include <cuda_runtime.h>
#include <math.h>
#include <float.h>
#include <stdint.h>

#define B_  16
#define M_  2
#define S_  1024
#define F_  32
#define D_  64
#define H_  4
#define K_  20
#define A_  10
#define HD_ (H_*D_)    /* 256 */
#define BM_ (B_*M_)    /* 32  */
#define NTOK_ (BM_*S_) /* 32768 */
#define NROWS_ (NTOK_*H_) /* 131072 q/k rows */

// ---------------- device scratch (static: no runtime allocation) -------------
__device__ float  g_h0 [NTOK_*100];
__device__ float  g_h1 [NTOK_*100];
__device__ float  g_enc[NTOK_*D_];
__device__ float  g_q  [NROWS_*D_];                 // 32 MB
__device__ float  g_k  [NROWS_*D_];                 // 32 MB
__device__ float4 g_afrag[(size_t)1024*32*128];     // 64 MB q tf32 fragments
__device__ float2 g_bfrag[(size_t)128*32*64*32];    // 64 MB k tf32 fragments
__device__ float  g_mse[M_*H_];

// packed f32x2 helpers (sm_103a FFMA2 — only reachable via PTX)
#define FFMA2(d,a,b,c) asm("fma.rn.f32x2 %0, %1, %2, %3;" : "=l"(d) : "l"(a), "l"(b), "l"(c))
#define PACK2(d,lo,hi) asm("mov.b64 %0, {%1, %2};"        : "=l"(d) : "f"(lo), "f"(hi))
#define UNPACK2(lo,hi,s) asm("mov.b64 {%0, %1}, %2;"      : "=f"(lo), "=f"(hi) : "l"(s))

// ---------------- tf32 helpers (sm_80 baseline ISA, ptxas-safe) ---------------
__device__ __forceinline__ uint32_t to_tf32(float x) {
    uint32_t r;
    asm("cvt.rna.tf32.f32 %0, %1;" : "=r"(r) : "f"(x));
    return r;
}
__device__ __forceinline__ void tf32_split(float x, uint32_t& hi, uint32_t& lo) {
    hi = to_tf32(x);
    lo = to_tf32(x - __uint_as_float(hi));
}
__device__ __forceinline__ void mma_tf32(float (&c)[4], const uint32_t (&a)[4],
                                         uint32_t b0, uint32_t b1) {
    asm volatile(
        "mma.sync.aligned.m16n8k8.row.col.f32.tf32.tf32.f32 "
        "{%0,%1,%2,%3}, {%4,%5,%6,%7}, {%8,%9}, {%0,%1,%2,%3};"
        : "+f"(c[0]), "+f"(c[1]), "+f"(c[2]), "+f"(c[3])
        : "r"(a[0]), "r"(a[1]), "r"(a[2]), "r"(a[3]), "r"(b0), "r"(b1));
}

// ---------------- MLP layer: 2-way output split + jg-pair FFMA2 ---------------
template<int IN, int OUT, bool RELU>
__global__ void __launch_bounds__(128)
mlp_kernel(const float* __restrict__ hin,
           const float* __restrict__ W,
           const float* __restrict__ bias,
           float* __restrict__ hout)
{
    constexpr int NG  = OUT/4;
    constexpr int NGH = (NG+1)/2;
    __shared__ float4 Wsm[IN*NGH];
    __shared__ float  bsm[OUT];

    const int tid = threadIdx.x;
    const int tok = blockIdx.x*128 + tid;
    const int m   = (tok >> 10) & (M_-1);
    const int jg0 = blockIdx.y * NGH;
    const int ng  = blockIdx.y ? (NG - NGH) : NGH;

    {
        const float* wb = W + (size_t)m*IN*OUT + jg0*4;
        for (int idx = tid; idx < IN*ng; idx += 128) {
            int i = idx / ng, c = idx - i*ng;
            Wsm[i*NGH + c] = *(const float4*)(wb + i*OUT + c*4);
        }
        for (int i = tid; i < OUT; i += 128) bsm[i] = bias[m*OUT + i];
    }
    __syncthreads();

    float r[IN];
    {
        const float4* hp = (const float4*)(hin + (size_t)tok*IN);
        #pragma unroll
        for (int i = 0; i < IN/4; i++) {
            float4 v = hp[i];
            r[4*i+0]=v.x; r[4*i+1]=v.y; r[4*i+2]=v.z; r[4*i+3]=v.w;
        }
    }

    float* houtrow = hout + (size_t)tok*OUT;

    int jg = 0;
    #pragma unroll 1
    for (; jg + 1 < ng; jg += 2) {
        unsigned long long acc[4];
        PACK2(acc[0], bsm[(jg0+jg)*4+0],   bsm[(jg0+jg)*4+1]);
        PACK2(acc[1], bsm[(jg0+jg)*4+2],   bsm[(jg0+jg)*4+3]);
        PACK2(acc[2], bsm[(jg0+jg+1)*4+0], bsm[(jg0+jg+1)*4+1]);
        PACK2(acc[3], bsm[(jg0+jg+1)*4+2], bsm[(jg0+jg+1)*4+3]);
        #pragma unroll
        for (int i = 0; i < IN; i++) {
            unsigned long long rr; PACK2(rr, r[i], r[i]);
            ulonglong2 w0 = *(const ulonglong2*)(Wsm + i*NGH + jg);
            ulonglong2 w1 = *(const ulonglong2*)(Wsm + i*NGH + jg + 1);
            FFMA2(acc[0], rr, w0.x, acc[0]);
            FFMA2(acc[1], rr, w0.y, acc[1]);
            FFMA2(acc[2], rr, w1.x, acc[2]);
            FFMA2(acc[3], rr, w1.y, acc[3]);
        }
        #pragma unroll
        for (int p = 0; p < 2; p++) {
            float a0,a1,a2,a3;
            UNPACK2(a0, a1, acc[2*p+0]);
            UNPACK2(a2, a3, acc[2*p+1]);
            if (RELU) {
                a0 = fmaxf(a0, 0.f); a1 = fmaxf(a1, 0.f);
                a2 = fmaxf(a2, 0.f); a3 = fmaxf(a3, 0.f);
            }
            *(float4*)(houtrow + (jg0+jg+p)*4) = make_float4(a0,a1,a2,a3);
        }
    }
    if (jg < ng) {
        unsigned long long acc[2];
        PACK2(acc[0], bsm[(jg0+jg)*4+0], bsm[(jg0+jg)*4+1]);
        PACK2(acc[1], bsm[(jg0+jg)*4+2], bsm[(jg0+jg)*4+3]);
        #pragma unroll
        for (int i = 0; i < IN; i++) {
            unsigned long long rr; PACK2(rr, r[i], r[i]);
            ulonglong2 w0 = *(const ulonglong2*)(Wsm + i*NGH + jg);
            FFMA2(acc[0], rr, w0.x, acc[0]);
            FFMA2(acc[1], rr, w0.y, acc[1]);
        }
        float a0,a1,a2,a3;
        UNPACK2(a0, a1, acc[0]);
        UNPACK2(a2, a3, acc[1]);
        if (RELU) {
            a0 = fmaxf(a0, 0.f); a1 = fmaxf(a1, 0.f);
            a2 = fmaxf(a2, 0.f); a3 = fmaxf(a3, 0.f);
        }
        *(float4*)(houtrow + (jg0+jg)*4) = make_float4(a0,a1,a2,a3);
    }
}

// ---------------- LN + q/k projections (flat, pass+col split, packed) ---------
#define PROJ2_SMEM_FLOATS (D_*(HD_/2) + 128)
#define PROJ2_SMEM_BYTES  (PROJ2_SMEM_FLOATS*4)

__global__ void __launch_bounds__(128)
proj2_kernel(const float* __restrict__ lnqg, const float* __restrict__ lnqb,
             const float* __restrict__ lnkg, const float* __restrict__ lnkb,
             const float* __restrict__ Wq,   const float* __restrict__ bq,
             const float* __restrict__ Wk,   const float* __restrict__ bk)
{
    extern __shared__ float psm[];
    float4* Wsm = (float4*)psm;
    float*  lnA = psm + D_*(HD_/2);

    const int tid  = threadIdx.x;
    const int tok  = blockIdx.x*128 + tid;
    const int by   = blockIdx.y;
    const int pass = blockIdx.z;
    const int bm   = tok >> 10;
    const int s    = tok & (S_-1);
    const int m    = bm & (M_-1);

    {
        const float* gsrc = pass ? lnkg : lnqg;
        const float* bsrc = pass ? lnkb : lnqb;
        lnA[tid] = (tid < 64) ? gsrc[m*D_ + tid] : bsrc[m*D_ + tid - 64];
        const float4* src = (const float4*)((pass ? Wk : Wq) + (size_t)m*D_*HD_);
        for (int idx = tid; idx < D_*32; idx += 128) {
            int i = idx >> 5, c = idx & 31;
            Wsm[i*32 + c] = src[i*64 + by*32 + c];
        }
    }

    float e[D_];
    {
        const float4* ep = (const float4*)(g_enc + (size_t)tok*D_);
        #pragma unroll
        for (int i = 0; i < D_/4; i++) {
            float4 v = ep[i];
            e[4*i+0]=v.x; e[4*i+1]=v.y; e[4*i+2]=v.z; e[4*i+3]=v.w;
        }
    }
    float mu = 0.f;
    #pragma unroll
    for (int d = 0; d < D_; d++) mu += e[d];
    mu *= (1.0f/D_);
    float var = 0.f;
    #pragma unroll
    for (int d = 0; d < D_; d++) { float x = e[d]-mu; var = fmaf(x,x,var); }
    var *= (1.0f/D_);
    const float rstd = rsqrtf(var + 1e-5f);

    __syncthreads();

    #pragma unroll
    for (int d = 0; d < D_; d++)
        e[d] = (e[d]-mu)*rstd * lnA[d] + lnA[64+d];

    const float* bop = (pass ? bk : bq) + m*HD_;
    float* outp      = pass ? g_k : g_q;

    #pragma unroll 1
    for (int st = 0; st < 4; st++) {
        const int G0 = by*32 + st*8;
        unsigned long long acc[16];
        #pragma unroll
        for (int j = 0; j < 8; j++) {
            float4 b4 = __ldg((const float4*)(bop + (G0+j)*4));
            PACK2(acc[2*j+0], b4.x, b4.y);
            PACK2(acc[2*j+1], b4.z, b4.w);
        }
        #pragma unroll 2
        for (int i = 0; i < D_; i++) {
            unsigned long long rr; PACK2(rr, e[i], e[i]);
            const ulonglong2* wrow = (const ulonglong2*)(Wsm + i*32 + st*8);
            #pragma unroll
            for (int j = 0; j < 8; j++) {
                ulonglong2 w = wrow[j];
                FFMA2(acc[2*j+0], rr, w.x, acc[2*j+0]);
                FFMA2(acc[2*j+1], rr, w.y, acc[2*j+1]);
            }
        }
        #pragma unroll
        for (int j = 0; j < 8; j++) {
            float a0,a1,a2,a3;
            UNPACK2(a0, a1, acc[2*j+0]);
            UNPACK2(a2, a3, acc[2*j+1]);
            const int G  = G0 + j;
            const int h  = G >> 4;
            const int d0 = (G & 15) * 4;
            *(float4*)(outp + ((size_t)(bm*H_ + h)*S_ + s)*D_ + d0)
                = make_float4(a0,a1,a2,a3);
        }
    }
}

// ---------------- fragment prep: q (A) and k (B) tf32 splits -------------------
// A fragment chunk layout: g_afrag[bk][c][tid], c = (2*mt+spl)*8 + k.
// Element order per float4: a0=(r,c) a1=(r+8,c) a2=(r,c+4) a3=(r+8,c+4),
// matching mma.m16n8k8 A-fragment (gid=lane>>2 rows, tig=lane&3 cols).
__global__ void __launch_bounds__(128) qfrag_kernel()
{
    const int tid = threadIdx.x;
    const int bk  = blockIdx.x;            // bmh*8 + yb
    const int bmh = bk >> 3, yb = bk & 7;
    const int w   = tid >> 5, lane = tid & 31;
    const int gid = lane >> 2, tig = lane & 3;

    float4* dst = g_afrag + (size_t)bk*4096;

    #pragma unroll
    for (int mt = 0; mt < 2; mt++) {
        const size_t r0 = (size_t)bmh*S_ + yb*128 + w*32 + mt*16 + gid;
        const float* q0 = g_q + r0*D_;
        const float* q1 = g_q + (r0+8)*D_;
        #pragma unroll
        for (int k = 0; k < 8; k++) {
            const int c0 = 8*k + tig;
            float v0 = 0.125f*q0[c0],     v1 = 0.125f*q1[c0];
            float v2 = 0.125f*q0[c0+4],   v3 = 0.125f*q1[c0+4];
            uint32_t h0,l0,h1,l1,h2,l2,h3,l3;
            tf32_split(v0,h0,l0); tf32_split(v1,h1,l1);
            tf32_split(v2,h2,l2); tf32_split(v3,h3,l3);
            dst[((2*mt+0)*8 + k)*128 + tid] = make_float4(
                __uint_as_float(h0), __uint_as_float(h1),
                __uint_as_float(h2), __uint_as_float(h3));
            dst[((2*mt+1)*8 + k)*128 + tid] = make_float4(
                __uint_as_float(l0), __uint_as_float(l1),
                __uint_as_float(l2), __uint_as_float(l3));
        }
    }
}

// B fragment chunk layout: g_bfrag[bmh][kt][cb][lane], cb = (nt*2+spl)*8 + k.
// float2 = {b0,b1}: b0 = B[dim=8k+tig][key=kt*32+nt*8+gid], b1 = dim+4.
__global__ void __launch_bounds__(128) kfrag_kernel()
{
    const int tid = threadIdx.x;
    const int bmh = blockIdx.x, kt = blockIdx.y;
    const int nt  = tid >> 5, lane = tid & 31;
    const int gid = lane >> 2, tig = lane & 3;

    const int key = kt*32 + nt*8 + gid;
    const float* kr = g_k + ((size_t)bmh*S_ + key)*D_;
    float2* dst = g_bfrag + ((size_t)bmh*32 + kt)*64*32;

    #pragma unroll
    for (int k = 0; k < 8; k++) {
        float kv0 = kr[8*k + tig];
        float kv1 = kr[8*k + tig + 4];
        uint32_t h0,l0,h1,l1;
        tf32_split(kv0,h0,l0); tf32_split(kv1,h1,l1);
        dst[((nt*2+0)*8 + k)*32 + lane] = make_float2(__uint_as_float(h0), __uint_as_float(h1));
        dst[((nt*2+1)*8 + k)*32 + lane] = make_float2(__uint_as_float(l0), __uint_as_float(l1));
    }
}

// ---------------- top-k insert (register-resident, static indices) -----------
__device__ __forceinline__ void topk_insert(float (&tv)[K_], int (&ti)[K_],
                                            float score, int tg)
{
    bool gt[K_];
    #pragma unroll
    for (int i = 0; i < K_; i++) gt[i] = (tv[i] < score);
    #pragma unroll
    for (int i = K_-1; i > 0; i--) {
        if (gt[i-1]) { tv[i] = tv[i-1]; ti[i] = ti[i-1]; }
    }
    #pragma unroll
    for (int i = 0; i < K_; i++) {
        bool place = gt[i] && ((i == 0) || !gt[i-1]);
        if (place) { tv[i] = score; ti[i] = tg; }
    }
}

// ---------------- kernel C: TF32 mma scores + top-k + quantiles + outputs ----
// grid (BM_*H_, 8), 128 threads. Warp w owns q rows [32w,32w+32) of the tile.
// 3xTF32: terms (A0,B0) (A1,B0) (A0,B1). Scores staged in warp-private smem
// rows; thread tid reads row tid -> existing batched top-k.
#define SC_PITCH 34
#define SCORE_SMEM_BYTES (65536 + 4096 + SC_PITCH*128*4 + 512)

__global__ void __launch_bounds__(128)
score_kernel(const float* __restrict__ Y, float* __restrict__ out)
{
    extern __shared__ float ssm[];
    float4* asm4 = (float4*)ssm;                // 4096 float4 = 64KB A fragments
    float*  ysm  = ssm + 16384;                 // 1024
    float*  scr  = ssm + 16384 + 1024;          // 128*34
    float*  red  = scr + SC_PITCH*128;          // 128

    const int tid = threadIdx.x;
    const int w   = tid >> 5, lane = tid & 31;
    const int gid = lane >> 2, tig = lane & 3;
    const int bmh = blockIdx.x;
    const int yb  = blockIdx.y;
    const int bm  = bmh / H_;
    const int h   = bmh % H_;
    const int b   = bm / M_;
    const int m   = bm % M_;
    const int s   = yb*128 + tid;

    // stage Y row + A fragments
    for (int i = tid; i < S_; i += 128) ysm[i] = Y[bm*S_ + i];
    {
        const float4* src = g_afrag + (size_t)(bmh*8 + yb)*4096;
        for (int i = tid; i < 4096; i += 128) asm4[i] = src[i];
    }
    __syncthreads();

    float tv[K_];
    int   ti[K_];
    #pragma unroll
    for (int i = 0; i < K_; i++) { tv[i] = -FLT_MAX; ti[i] = 0; }
    float vmin = -FLT_MAX;

    const float2* bfrag = g_bfrag + (size_t)bmh*32*64*32;
    const int row0 = w*32 + gid;          // this thread's C row (mt=0), +16 for mt=1

    #pragma unroll 1
    for (int kt = 0; kt < 32; kt++) {
        float c[2][4][4];
        #pragma unroll
        for (int mt = 0; mt < 2; mt++)
            #pragma unroll
            for (int nt = 0; nt < 4; nt++)
                #pragma unroll
                for (int i = 0; i < 4; i++) c[mt][nt][i] = 0.f;

        const float2* bt = bfrag + (size_t)kt*2048;

        #pragma unroll
        for (int k = 0; k < 8; k++) {
            uint32_t Af[2][2][4];
            #pragma unroll
            for (int mt = 0; mt < 2; mt++)
                #pragma unroll
                for (int spl = 0; spl < 2; spl++) {
                    float4 av = asm4[((2*mt+spl)*8 + k)*128 + tid];
                    Af[mt][spl][0] = __float_as_uint(av.x);
                    Af[mt][spl][1] = __float_as_uint(av.y);
                    Af[mt][spl][2] = __float_as_uint(av.z);
                    Af[mt][spl][3] = __float_as_uint(av.w);
                }
            uint32_t B0[4][2], B1[4][2];
            #pragma unroll
            for (int nt = 0; nt < 4; nt++) {
                float2 bh = __ldg(bt + ((nt*2+0)*8 + k)*32 + lane);
                float2 bl = __ldg(bt + ((nt*2+1)*8 + k)*32 + lane);
                B0[nt][0] = __float_as_uint(bh.x); B0[nt][1] = __float_as_uint(bh.y);
                B1[nt][0] = __float_as_uint(bl.x); B1[nt][1] = __float_as_uint(bl.y);
            }
            #pragma unroll
            for (int mt = 0; mt < 2; mt++)
                #pragma unroll
                for (int nt = 0; nt < 4; nt++) {
                    mma_tf32(c[mt][nt], Af[mt][0], B0[nt][0], B0[nt][1]);
                    mma_tf32(c[mt][nt], Af[mt][1], B0[nt][0], B0[nt][1]);
                    mma_tf32(c[mt][nt], Af[mt][0], B1[nt][0], B1[nt][1]);
                }
        }

        // scatter C to warp-private smem rows
        #pragma unroll
        for (int mt = 0; mt < 2; mt++) {
            const int r = row0 + mt*16;
            #pragma unroll
            for (int nt = 0; nt < 4; nt++) {
                const int col = nt*8 + 2*tig;
                *(float2*)(scr + r*SC_PITCH + col)     = make_float2(c[mt][nt][0], c[mt][nt][1]);
                *(float2*)(scr + (r+8)*SC_PITCH + col) = make_float2(c[mt][nt][2], c[mt][nt][3]);
            }
        }
        __syncwarp();

        // top-k over this thread's row (32 scores), 4 groups of 8
        const float2* srow = (const float2*)(scr + tid*SC_PITCH);
        #pragma unroll
        for (int g = 0; g < 4; g++) {
            float sc[8];
            #pragma unroll
            for (int i = 0; i < 4; i++) {
                float2 v = srow[g*4 + i];
                sc[2*i] = v.x; sc[2*i+1] = v.y;
            }
            float m0 = fmaxf(sc[0], sc[1]); int j0 = (sc[1] > sc[0]) ? 1 : 0;
            float m1 = fmaxf(sc[2], sc[3]); int j1 = (sc[3] > sc[2]) ? 3 : 2;
            float m2 = fmaxf(sc[4], sc[5]); int j2 = (sc[5] > sc[4]) ? 5 : 4;
            float m3 = fmaxf(sc[6], sc[7]); int j3 = (sc[7] > sc[6]) ? 7 : 6;
            float n0 = fmaxf(m0, m1);  int p0 = (m1 > m0) ? j1 : j0;
            float n1 = fmaxf(m2, m3);  int p1 = (m3 > m2) ? j3 : j2;
            float gm = fmaxf(n0, n1);  int gi = (n1 > n0) ? p1 : p0;

            const int base = kt*32 + g*8;
            while (gm > vmin) {
                topk_insert(tv, ti, gm, base + gi);
                vmin = tv[K_-1];
                #pragma unroll
                for (int j = 0; j < 8; j++) {
                    if (j == gi) sc[j] = -FLT_MAX;
                }
                m0 = fmaxf(sc[0], sc[1]); j0 = (sc[1] > sc[0]) ? 1 : 0;
                m1 = fmaxf(sc[2], sc[3]); j1 = (sc[3] > sc[2]) ? 3 : 2;
                m2 = fmaxf(sc[4], sc[5]); j2 = (sc[5] > sc[4]) ? 5 : 4;
                m3 = fmaxf(sc[6], sc[7]); j3 = (sc[7] > sc[6]) ? 7 : 6;
                n0 = fmaxf(m0, m1);  p0 = (m1 > m0) ? j1 : j0;
                n1 = fmaxf(m2, m3);  p1 = (m3 > m2) ? j3 : j2;
                gm = fmaxf(n0, n1);  gi = (n1 > n0) ? p1 : p0;
            }
        }
        __syncwarp();   // reads done before next tile overwrites scr
    }

    // gather selected Y values
    float yv[K_];
    #pragma unroll
    for (int i = 0; i < K_; i++) yv[i] = ysm[ti[i]];

    // ascending sort: unrolled bubble network
    #pragma unroll
    for (int i = 0; i < K_-1; i++) {
        #pragma unroll
        for (int j = 0; j < K_-1-i; j++) {
            float a = yv[j], c2 = yv[j+1];
            yv[j]   = fminf(a, c2);
            yv[j+1] = fmaxf(a, c2);
        }
    }

    constexpr float QS[2*A_] = {
        0.025f,0.03f,0.04f,0.05f,0.06f,0.07f,0.075f,0.085f,0.095f,0.1f,
        0.975f,0.97f,0.96f,0.95f,0.94f,0.93f,0.925f,0.915f,0.905f,0.9f };
    float qv[2*A_];
    float qsum = 0.f;
    #pragma unroll
    for (int i = 0; i < 2*A_; i++) {
        const float hp = QS[i] * (float)(K_-1);
        const int   lo = ((int)hp > K_-2) ? (K_-2) : (int)hp;
        const float fr = hp - (float)lo;
        float v = yv[lo] + (yv[lo+1] - yv[lo]) * fr;
        qv[i] = v; qsum += v;
    }
    float ypred = qsum * (1.0f/(2*A_));

    float* out_low  = out + M_ + B_*S_*M_;
    float* out_high = out_low + (size_t)H_*B_*A_*S_*M_;
    #pragma unroll
    for (int a = 0; a < A_; a++) {
        size_t off = (((size_t)((h*B_ + b)*A_ + a))*S_ + s)*M_ + m;
        out_low [off] = qv[a];
        out_high[off] = qv[a + A_];
    }

    float yt = ysm[s];
    float d  = yt - ypred;
    red[tid] = d*d;
    __syncthreads();
    for (int off = 64; off > 0; off >>= 1) {
        if (tid < off) red[tid] += red[tid+off];
        __syncthreads();
    }
    if (tid == 0) atomicAdd(&g_mse[m*H_ + h], red[0]);
}

// ---------------- small kernels ----------------------------------------------
__global__ void init_kernel()
{
    if (threadIdx.x < M_*H_) g_mse[threadIdx.x] = 0.f;
}

__global__ void finalize_kernel(float* __restrict__ out)
{
    if (threadIdx.x < M_) {
        int m = threadIdx.x;
        float sacc = 0.f;
        for (int h = 0; h < H_; h++) sacc += g_mse[m*H_ + h];
        out[m] = sacc / (float)(B_*S_*H_);
    }
}

__global__ void yout_kernel(const float* __restrict__ Y, float* __restrict__ out)
{
    int i = blockIdx.x*blockDim.x + threadIdx.x;
    if (i < B_*S_*M_) {
        int m = i % M_;
        int s = (i / M_) % S_;
        int b = i / (M_*S_);
        out[M_ + i] = Y[((size_t)(b*M_ + m))*S_ + s];
    }
}

// ---------------- launch ------------------------------------------------------
extern "C" void kernel_launch(void* const* d_in, const int* in_sizes, int n_in,
                              void* d_out, int out_size)
{
    (void)in_sizes; (void)n_in; (void)out_size;
    const float* X    = (const float*)d_in[0];
    const float* Y    = (const float*)d_in[1];
    const float* W0   = (const float*)d_in[2];
    const float* b0   = (const float*)d_in[3];
    const float* W1   = (const float*)d_in[4];
    const float* b1   = (const float*)d_in[5];
    const float* W2   = (const float*)d_in[6];
    const float* b2   = (const float*)d_in[7];
    const float* W3   = (const float*)d_in[8];
    const float* b3   = (const float*)d_in[9];
    const float* lnqg = (const float*)d_in[10];
    const float* lnqb = (const float*)d_in[11];
    const float* lnkg = (const float*)d_in[12];
    const float* lnkb = (const float*)d_in[13];
    const float* Wq   = (const float*)d_in[14];
    const float* bq   = (const float*)d_in[15];
    const float* Wk   = (const float*)d_in[16];
    const float* bk   = (const float*)d_in[17];
    float* out = (float*)d_out;

    cudaFuncSetAttribute(proj2_kernel, cudaFuncAttributeMaxDynamicSharedMemorySize, PROJ2_SMEM_BYTES);
    cudaFuncSetAttribute(score_kernel, cudaFuncAttributeMaxDynamicSharedMemorySize, SCORE_SMEM_BYTES);

    float* h0p; cudaGetSymbolAddress((void**)&h0p, g_h0);
    float* h1p; cudaGetSymbolAddress((void**)&h1p, g_h1);
    float* enp; cudaGetSymbolAddress((void**)&enp, g_enc);

    const int NB = NTOK_/128;   // 256 blocks
    dim3 gm(NB, 2);
    dim3 gp(NB, 2, 2);

    init_kernel<<<1, 32>>>();
    mlp_kernel<F_, 100, true ><<<gm, 128>>>(X,   W0, b0, h0p);
    mlp_kernel<100, 100, true ><<<gm, 128>>>(h0p, W1, b1, h1p);
    mlp_kernel<100, 100, true ><<<gm, 128>>>(h1p, W2, b2, h0p);
    mlp_kernel<100, D_, false><<<gm, 128>>>(h0p, W3, b3, enp);
    proj2_kernel<<<gp, 128, PROJ2_SMEM_BYTES>>>(lnqg,lnqb, lnkg,lnkb, Wq,bq, Wk,bk);
    qfrag_kernel<<<1024, 128>>>();
    dim3 gk(128, 32);
    kfrag_kernel<<<gk, 128>>>();
    dim3 gc(BM_*H_, 8);
    score_kernel<<<gc, 128, SCORE_SMEM_BYTES>>>(Y, out);
    finalize_kernel<<<1, 32>>>(out);
    yout_kernel<<<(B_*S_*M_ + 255)/256, 256>>>(Y, out);
}